// round 2
// baseline (speedup 1.0000x reference)
#include <cuda_runtime.h>
#include <math.h>

// ---------------- problem constants ----------------
#define NE   512          // NUM_EMBED
#define ED   64           // EMBED_DIM
#define NTOK 131072       // 32*64*64 tokens
#define HW   4096         // 64*64 spatial per image
#define CODE_CHUNK 32
#define FIX_TAU 1e-3f     // top-2 gap threshold for fp64 fixup

// ---------------- output layout (flattened tuple, float32) ----------------
// (loss, out, perplexity, encodings, new_embedding, cluster, new_ema_w)
static constexpr size_t OFF_LOSS    = 0;
static constexpr size_t OFF_OUT     = 1;                       // 8388608 elems
static constexpr size_t OFF_PERP    = 1 + 8388608ull;          // 8388609
static constexpr size_t OFF_ENC     = OFF_PERP + 1;            // 67108864 elems
static constexpr size_t OFF_NEWEMB  = OFF_ENC + (size_t)NTOK * NE;
static constexpr size_t OFF_CLUSTER = OFF_NEWEMB + (size_t)NE * ED;
static constexpr size_t OFF_NEWEMAW = OFF_CLUSTER + NE;

// ---------------- device scratch (no allocations allowed) ----------------
__device__ float g_counts[NE];
__device__ float g_dw[NE * ED];
__device__ float g_loss;
__device__ float g_ne[NE];
__device__ int   g_bid[NTOK];
__device__ int   g_fix_list[NTOK];
__device__ int   g_fix_count;

__device__ __forceinline__ float warpSum(float v) {
    v += __shfl_xor_sync(0xffffffffu, v, 16);
    v += __shfl_xor_sync(0xffffffffu, v, 8);
    v += __shfl_xor_sync(0xffffffffu, v, 4);
    v += __shfl_xor_sync(0xffffffffu, v, 2);
    v += __shfl_xor_sync(0xffffffffu, v, 1);
    return v;
}

// ---------------- init: code norms + zero scratch ----------------
__global__ void vq_init(const float* __restrict__ emb) {
    int e = threadIdx.x;   // 512 threads
    float s = 0.f;
#pragma unroll
    for (int d = 0; d < ED; d++) {
        float v = emb[e * ED + d];
        s = fmaf(v, v, s);
    }
    g_ne[e] = s;
    g_counts[e] = 0.f;
#pragma unroll
    for (int j = 0; j < ED; j++) g_dw[j * NE + e] = 0.f;
    if (e == 0) { g_loss = 0.f; g_fix_count = 0; }
}

// ---------------- pass A: fast fp32 argmin + top-2 gap flagging ----------------
__global__ __launch_bounds__(128)
void vq_argmin(const float* __restrict__ x, const float* __restrict__ emb) {
    __shared__ float es[CODE_CHUNK * ED];   // 8 KB: code chunk, [c][d]
    __shared__ float nes[CODE_CHUNK];

    const int t   = threadIdx.x;
    const int blk = blockIdx.x;
    const int b   = blk >> 5;           // image index
    const int s0  = (blk & 31) * 128;   // spatial offset

    // Direct coalesced NCHW loads into registers
    const float* xb = x + ((size_t)b * ED) * HW + s0;
    float f[ED];
#pragma unroll
    for (int d = 0; d < ED; d++) f[d] = xb[(size_t)d * HW + t];

    float best = 3.4e38f, second = 3.4e38f;
    int   bid  = 0;

    for (int c0 = 0; c0 < NE; c0 += CODE_CHUNK) {
        __syncthreads();
#pragma unroll
        for (int k = 0; k < (CODE_CHUNK * ED / 128); k++)
            es[k * 128 + t] = emb[c0 * ED + k * 128 + t];
        if (t < CODE_CHUNK) nes[t] = g_ne[c0 + t];
        __syncthreads();

        for (int c = 0; c < CODE_CHUNK; c++) {
            const float4* e4 = (const float4*)(es + c * ED);
            float a0 = 0.f, a1 = 0.f, a2 = 0.f, a3 = 0.f;
#pragma unroll
            for (int j = 0; j < 16; j++) {
                float4 ev = e4[j];   // broadcast LDS.128
                a0 = fmaf(f[4 * j + 0], ev.x, a0);
                a1 = fmaf(f[4 * j + 1], ev.y, a1);
                a2 = fmaf(f[4 * j + 2], ev.z, a2);
                a3 = fmaf(f[4 * j + 3], ev.w, a3);
            }
            float dist = nes[c] - 2.f * ((a0 + a1) + (a2 + a3));
            if (dist < best)        { second = best; best = dist; bid = c0 + c; }
            else if (dist < second) { second = dist; }
        }
    }

    const int n = blk * 128 + t;
    g_bid[n] = bid;
    if (second - best < FIX_TAU) {
        int i = atomicAdd(&g_fix_count, 1);
        g_fix_list[i] = n;
    }
}

// ---------------- pass B: fp64 fixup of near-tie tokens ----------------
// Mimics the reference: distances rounded to fp32 via ((sf+se) - 2*dot),
// argmin with tie -> lowest index.
__global__ void vq_fixup(const float* __restrict__ x, const float* __restrict__ emb) {
    const int lane = threadIdx.x & 31;
    const int gw   = (blockIdx.x * blockDim.x + threadIdx.x) >> 5;
    const int nw   = (gridDim.x * blockDim.x) >> 5;
    const int cnt  = g_fix_count;

    for (int i = gw; i < cnt; i += nw) {
        const int n = g_fix_list[i];
        const int b = n >> 12;
        const int s = n & 4095;

        float f[ED];
#pragma unroll
        for (int d = 0; d < ED; d++)
            f[d] = x[((size_t)b * ED + d) * HW + s];

        double sf = 0.0;
#pragma unroll
        for (int d = 0; d < ED; d++) sf = fma((double)f[d], (double)f[d], sf);

        float bestd = 3.4e38f;
        int   bestc = NE;
        for (int j = 0; j < NE / 32; j++) {
            const int c = lane + 32 * j;           // ascending per lane
            const float* e = emb + (size_t)c * ED;
            double dot = 0.0, se = 0.0;
#pragma unroll
            for (int d = 0; d < ED; d++) {
                double ev = (double)e[d];
                dot = fma((double)f[d], ev, dot);
                se  = fma(ev, ev, se);
            }
            float t1  = (float)(sf + se);
            float t2  = (float)(2.0 * dot);
            float d32 = t1 - t2;                    // fp32 rounding like reference
            if (d32 < bestd || (d32 == bestd && c < bestc)) { bestd = d32; bestc = c; }
        }
        // lexicographic warp argmin (value, then index)
#pragma unroll
        for (int off = 16; off >= 1; off >>= 1) {
            float od = __shfl_xor_sync(0xffffffffu, bestd, off);
            int   oc = __shfl_xor_sync(0xffffffffu, bestc, off);
            if (od < bestd || (od == bestd && oc < bestc)) { bestd = od; bestc = oc; }
        }
        if (lane == 0) g_bid[n] = bestc;
    }
}

// ---------------- pass C: outputs (one-hot, quantized ST, dw, counts, loss) ----------------
__global__ __launch_bounds__(128)
void vq_write(const float* __restrict__ x, const float* __restrict__ emb,
              float* __restrict__ out) {
    const int t   = threadIdx.x;
    const int blk = blockIdx.x;
    const int b   = blk >> 5;
    const int s0  = (blk & 31) * 128;
    const int n   = blk * 128 + t;

    const float* xb = x + ((size_t)b * ED) * HW + s0;
    float f[ED];
#pragma unroll
    for (int d = 0; d < ED; d++) f[d] = xb[(size_t)d * HW + t];

    const int bid = g_bid[n];

    // one-hot (region pre-zeroed by memset)
    out[OFF_ENC + (size_t)n * NE + bid] = 1.0f;

    // cluster count + dw scatter
    atomicAdd(&g_counts[bid], 1.0f);
#pragma unroll
    for (int d = 0; d < ED; d++) atomicAdd(&g_dw[bid * ED + d], f[d]);

    // quantized straight-through output (NCHW) + commitment-loss partial
    float lsum = 0.f;
    const float4* ev4 = (const float4*)(emb + (size_t)bid * ED);
    float* ob = out + OFF_OUT + ((size_t)b * ED) * HW + s0;
#pragma unroll
    for (int j = 0; j < 16; j++) {
        float4 ev = __ldg(ev4 + j);
        float d0 = ev.x - f[4 * j + 0];
        float d1 = ev.y - f[4 * j + 1];
        float d2 = ev.z - f[4 * j + 2];
        float d3 = ev.w - f[4 * j + 3];
        lsum += d0 * d0 + d1 * d1 + d2 * d2 + d3 * d3;
        // straight-through: fl(f + fl(q - f)), matching the reference's rounding
        ob[(size_t)(4 * j + 0) * HW + t] = f[4 * j + 0] + d0;
        ob[(size_t)(4 * j + 1) * HW + t] = f[4 * j + 1] + d1;
        ob[(size_t)(4 * j + 2) * HW + t] = f[4 * j + 2] + d2;
        ob[(size_t)(4 * j + 3) * HW + t] = f[4 * j + 3] + d3;
    }
    lsum = warpSum(lsum);
    if ((t & 31) == 0) atomicAdd(&g_loss, lsum);
}

// ---------------- finalize: EMA updates, loss, perplexity ----------------
__global__ void vq_final(const float* __restrict__ ema_w,
                         const float* __restrict__ ecs,
                         float* __restrict__ out) {
    __shared__ float red[16];
    __shared__ float cl[NE];
    __shared__ float kkb;

    const int e = threadIdx.x;     // 512 threads
    const int lane = e & 31, w = e >> 5;

    float cnt = g_counts[e];
    float c   = ecs[e] * 0.99f + 0.01f * cnt;

    // k = sum(cluster)
    float s = warpSum(c);
    if (lane == 0) red[w] = s;
    __syncthreads();
    if (w == 0) {
        float v = (lane < 16) ? red[lane] : 0.f;
        v = warpSum(v);
        if (lane == 0) kkb = v;
    }
    __syncthreads();
    const float k = kkb;

    float cs = (c + 1e-5f) / (k + 512.f * 1e-5f) * k;   // Laplace smoothing
    cl[e] = cs;
    out[OFF_CLUSTER + e] = cs;

    // perplexity
    float p = cnt * (1.f / 131072.f);
    float term = p * logf(p + 1e-10f);
    float s2 = warpSum(term);
    __syncthreads();
    if (lane == 0) red[w] = s2;
    __syncthreads();
    if (e == 0) {
        float v = 0.f;
        for (int i = 0; i < 16; i++) v += red[i];
        out[OFF_PERP] = expf(-v);
        out[OFF_LOSS] = 0.25f * g_loss * (1.f / 8388608.f);
    }
    __syncthreads();

    // new_ema_w and new_embedding (coalesced)
    for (int m = e; m < NE * ED; m += 512) {
        float wv = ema_w[m] * 0.99f + 0.01f * g_dw[m];
        out[OFF_NEWEMAW + m] = wv;
        out[OFF_NEWEMB  + m] = wv / cl[m >> 6];
    }
}

// ---------------- launch ----------------
extern "C" void kernel_launch(void* const* d_in, const int* in_sizes, int n_in,
                              void* d_out, int out_size) {
    const float* x     = (const float*)d_in[0];
    const float* emb   = (const float*)d_in[1];
    const float* ema_w = (const float*)d_in[2];
    const float* ecs   = (const float*)d_in[3];
    float* out = (float*)d_out;

    // zero the one-hot region at full HBM rate
    cudaMemsetAsync(out + OFF_ENC, 0, (size_t)NTOK * NE * sizeof(float));

    vq_init<<<1, NE>>>(emb);
    vq_argmin<<<NTOK / 128, 128>>>(x, emb);
    vq_fixup<<<148, 128>>>(x, emb);
    vq_write<<<NTOK / 128, 128>>>(x, emb, out);
    vq_final<<<1, NE>>>(ema_w, ecs, out);
}

// round 4
// speedup vs baseline: 1.0288x; 1.0288x over previous
#include <cuda_runtime.h>
#include <math.h>

// ---------------- problem constants ----------------
#define NE   512          // NUM_EMBED
#define ED   64           // EMBED_DIM
#define NTOK 131072       // 32*64*64 tokens
#define HW   4096         // 64*64 spatial per image
#define CODE_CHUNK 32
#define FIX_TAU 1e-3f     // top-2 gap threshold for fp64 fixup

// ---------------- output layout (flattened tuple, float32) ----------------
static constexpr size_t OFF_LOSS    = 0;
static constexpr size_t OFF_OUT     = 1;                       // 8388608 elems
static constexpr size_t OFF_PERP    = 1 + 8388608ull;
static constexpr size_t OFF_ENC     = OFF_PERP + 1;            // 67108864 elems (8-byte aligned only!)
static constexpr size_t OFF_NEWEMB  = OFF_ENC + (size_t)NTOK * NE;
static constexpr size_t OFF_CLUSTER = OFF_NEWEMB + (size_t)NE * ED;
static constexpr size_t OFF_NEWEMAW = OFF_CLUSTER + NE;

// ---------------- device scratch ----------------
__device__ float g_counts[NE];
__device__ float g_dw[NE * ED];
__device__ float g_loss;
__device__ float g_ne[NE];
__device__ int   g_bid[NTOK];
__device__ int   g_fix_list[NTOK];
__device__ int   g_fix_count;

__device__ __forceinline__ float warpSum(float v) {
    v += __shfl_xor_sync(0xffffffffu, v, 16);
    v += __shfl_xor_sync(0xffffffffu, v, 8);
    v += __shfl_xor_sync(0xffffffffu, v, 4);
    v += __shfl_xor_sync(0xffffffffu, v, 2);
    v += __shfl_xor_sync(0xffffffffu, v, 1);
    return v;
}

// ---------------- init: code norms + zero scratch ----------------
__global__ void vq_init(const float* __restrict__ emb) {
    int e = threadIdx.x;   // 512 threads
    float s = 0.f;
#pragma unroll
    for (int d = 0; d < ED; d++) {
        float v = emb[e * ED + d];
        s = fmaf(v, v, s);
    }
    g_ne[e] = s;
    g_counts[e] = 0.f;
#pragma unroll
    for (int j = 0; j < ED; j++) g_dw[j * NE + e] = 0.f;
    if (e == 0) { g_loss = 0.f; g_fix_count = 0; }
}

// ---------------- fused: zero enc rows + argmin + all outputs ----------------
__global__ __launch_bounds__(128)
void vq_fused(const float* __restrict__ x, const float* __restrict__ emb,
              float* __restrict__ out) {
    __shared__ float es[CODE_CHUNK * ED];   // 8 KB code chunk [c][d]
    __shared__ float nes[CODE_CHUNK];

    const int t   = threadIdx.x;
    const int blk = blockIdx.x;
    const int b   = blk >> 5;           // image index
    const int s0  = (blk & 31) * 128;   // spatial offset
    const int n0  = blk * 128;          // block token base

    // Zero this block's 128 encodings rows (contiguous 256 KB, coalesced).
    // OFF_ENC is only 8-byte aligned -> float2 stores (STG.64), NOT float4.
    {
        float2 z = make_float2(0.f, 0.f);
        float2* enc2 = (float2*)(out + OFF_ENC + (size_t)n0 * NE);
#pragma unroll 8
        for (int i = t; i < 128 * NE / 2; i += 128) enc2[i] = z;
    }

    // Coalesced NCHW loads into registers
    const float* xb = x + ((size_t)b * ED) * HW + s0;
    float f[ED];
#pragma unroll
    for (int d = 0; d < ED; d++) f[d] = xb[(size_t)d * HW + t];

    float best = 3.4e38f, second = 3.4e38f;
    int   bid  = 0;

    for (int c0 = 0; c0 < NE; c0 += CODE_CHUNK) {
        __syncthreads();
#pragma unroll
        for (int k = 0; k < (CODE_CHUNK * ED / 128); k++)
            es[k * 128 + t] = emb[c0 * ED + k * 128 + t];
        if (t < CODE_CHUNK) nes[t] = g_ne[c0 + t];
        __syncthreads();

        for (int c = 0; c < CODE_CHUNK; c++) {
            const float4* e4 = (const float4*)(es + c * ED);
            float a0 = 0.f, a1 = 0.f, a2 = 0.f, a3 = 0.f;
#pragma unroll
            for (int j = 0; j < 16; j++) {
                float4 ev = e4[j];   // broadcast LDS.128
                a0 = fmaf(f[4 * j + 0], ev.x, a0);
                a1 = fmaf(f[4 * j + 1], ev.y, a1);
                a2 = fmaf(f[4 * j + 2], ev.z, a2);
                a3 = fmaf(f[4 * j + 3], ev.w, a3);
            }
            float dist = nes[c] - 2.f * ((a0 + a1) + (a2 + a3));
            if (dist < best)        { second = best; best = dist; bid = c0 + c; }
            else if (dist < second) { second = dist; }
        }
    }

    const int n = n0 + t;
    g_bid[n] = bid;
    if (second - best < FIX_TAU) {
        int i = atomicAdd(&g_fix_count, 1);
        g_fix_list[i] = n;
    }

    // one-hot (own block's rows, zeroed above; __syncthreads in loop ordered it)
    out[OFF_ENC + (size_t)n * NE + bid] = 1.0f;

    // cluster count + dw scatter (fire-and-forget REDG, hidden under FFMA)
    atomicAdd(&g_counts[bid], 1.0f);
#pragma unroll
    for (int d = 0; d < ED; d++) atomicAdd(&g_dw[bid * ED + d], f[d]);

    // straight-through output (NCHW) + commitment-loss partial
    float lsum = 0.f;
    const float4* ev4 = (const float4*)(emb + (size_t)bid * ED);
    float* ob = out + OFF_OUT + ((size_t)b * ED) * HW + s0;
#pragma unroll
    for (int j = 0; j < 16; j++) {
        float4 ev = __ldg(ev4 + j);
        float d0 = ev.x - f[4 * j + 0];
        float d1 = ev.y - f[4 * j + 1];
        float d2 = ev.z - f[4 * j + 2];
        float d3 = ev.w - f[4 * j + 3];
        lsum += d0 * d0 + d1 * d1 + d2 * d2 + d3 * d3;
        ob[(size_t)(4 * j + 0) * HW + t] = f[4 * j + 0] + d0;   // fl(f + fl(q-f))
        ob[(size_t)(4 * j + 1) * HW + t] = f[4 * j + 1] + d1;
        ob[(size_t)(4 * j + 2) * HW + t] = f[4 * j + 2] + d2;
        ob[(size_t)(4 * j + 3) * HW + t] = f[4 * j + 3] + d3;
    }
    lsum = warpSum(lsum);
    if ((t & 31) == 0) atomicAdd(&g_loss, lsum);
}

// ---------------- fixup: fp64 re-argmin of near-ties + delta patching ----------------
__global__ void vq_fixup(const float* __restrict__ x, const float* __restrict__ emb,
                         float* __restrict__ out) {
    const int lane = threadIdx.x & 31;
    const int gw   = (blockIdx.x * blockDim.x + threadIdx.x) >> 5;
    const int nw   = (gridDim.x * blockDim.x) >> 5;
    const int cnt  = g_fix_count;

    for (int i = gw; i < cnt; i += nw) {
        const int n = g_fix_list[i];
        const int b = n >> 12;
        const int s = n & 4095;

        float f[ED];
#pragma unroll
        for (int d = 0; d < ED; d++)
            f[d] = x[((size_t)b * ED + d) * HW + s];

        double sf = 0.0;
#pragma unroll
        for (int d = 0; d < ED; d++) sf = fma((double)f[d], (double)f[d], sf);

        float bestd = 3.4e38f;
        int   bestc = NE;
        for (int j = 0; j < NE / 32; j++) {
            const int c = lane + 32 * j;
            const float* e = emb + (size_t)c * ED;
            double dot = 0.0, se = 0.0;
#pragma unroll
            for (int d = 0; d < ED; d++) {
                double ev = (double)e[d];
                dot = fma((double)f[d], ev, dot);
                se  = fma(ev, ev, se);
            }
            float t1  = (float)(sf + se);
            float t2  = (float)(2.0 * dot);
            float d32 = t1 - t2;                    // fp32 rounding like reference
            if (d32 < bestd || (d32 == bestd && c < bestc)) { bestd = d32; bestc = c; }
        }
#pragma unroll
        for (int off = 16; off >= 1; off >>= 1) {
            float od = __shfl_xor_sync(0xffffffffu, bestd, off);
            int   oc = __shfl_xor_sync(0xffffffffu, bestc, off);
            if (od < bestd || (od == bestd && oc < bestc)) { bestd = od; bestc = oc; }
        }
        bestc = __shfl_sync(0xffffffffu, bestc, 0);

        const int oldb = g_bid[n];
        if (bestc != oldb) {
            if (lane == 0) {
                g_bid[n] = bestc;
                out[OFF_ENC + (size_t)n * NE + oldb]  = 0.0f;
                out[OFF_ENC + (size_t)n * NE + bestc] = 1.0f;
                atomicAdd(&g_counts[oldb], -1.0f);
                atomicAdd(&g_counts[bestc], 1.0f);
            }
            float delta = 0.f;
            for (int d = lane; d < ED; d += 32) {
                float eo = emb[(size_t)oldb  * ED + d];
                float en = emb[(size_t)bestc * ED + d];
                atomicAdd(&g_dw[oldb  * ED + d], -f[d]);
                atomicAdd(&g_dw[bestc * ED + d],  f[d]);
                float dn = en - f[d];
                float dold = eo - f[d];
                delta += dn * dn - dold * dold;
                out[OFF_OUT + ((size_t)b * ED + d) * HW + s] = f[d] + dn;
            }
            delta = warpSum(delta);
            if (lane == 0) atomicAdd(&g_loss, delta);
        }
    }
}

// ---------------- finalize: EMA updates, loss, perplexity ----------------
__global__ void vq_final(const float* __restrict__ ema_w,
                         const float* __restrict__ ecs,
                         float* __restrict__ out) {
    __shared__ float red[16];
    __shared__ float cl[NE];
    __shared__ float kkb;

    const int e = threadIdx.x;     // 512 threads
    const int lane = e & 31, w = e >> 5;

    float cnt = g_counts[e];
    float c   = ecs[e] * 0.99f + 0.01f * cnt;

    float s = warpSum(c);
    if (lane == 0) red[w] = s;
    __syncthreads();
    if (w == 0) {
        float v = (lane < 16) ? red[lane] : 0.f;
        v = warpSum(v);
        if (lane == 0) kkb = v;
    }
    __syncthreads();
    const float k = kkb;

    float cs = (c + 1e-5f) / (k + 512.f * 1e-5f) * k;   // Laplace smoothing
    cl[e] = cs;
    out[OFF_CLUSTER + e] = cs;

    float p = cnt * (1.f / 131072.f);
    float term = p * logf(p + 1e-10f);
    float s2 = warpSum(term);
    __syncthreads();
    if (lane == 0) red[w] = s2;
    __syncthreads();
    if (e == 0) {
        float v = 0.f;
        for (int i = 0; i < 16; i++) v += red[i];
        out[OFF_PERP] = expf(-v);
        out[OFF_LOSS] = 0.25f * g_loss * (1.f / 8388608.f);
    }
    __syncthreads();

    for (int m = e; m < NE * ED; m += 512) {
        float wv = ema_w[m] * 0.99f + 0.01f * g_dw[m];
        out[OFF_NEWEMAW + m] = wv;
        out[OFF_NEWEMB  + m] = wv / cl[m >> 6];
    }
}

// ---------------- launch ----------------
extern "C" void kernel_launch(void* const* d_in, const int* in_sizes, int n_in,
                              void* d_out, int out_size) {
    const float* x     = (const float*)d_in[0];
    const float* emb   = (const float*)d_in[1];
    const float* ema_w = (const float*)d_in[2];
    const float* ecs   = (const float*)d_in[3];
    float* out = (float*)d_out;

    vq_init<<<1, NE>>>(emb);
    vq_fused<<<NTOK / 128, 128>>>(x, emb, out);
    vq_fixup<<<148, 128>>>(x, emb, out);
    vq_final<<<1, NE>>>(ema_w, ecs, out);
}

// round 5
// speedup vs baseline: 1.3442x; 1.3066x over previous
#include <cuda_runtime.h>
#include <math.h>

// ---------------- problem constants ----------------
#define NE   512          // NUM_EMBED
#define ED   64           // EMBED_DIM
#define NTOK 131072       // 32*64*64 tokens
#define HW   4096         // 64*64 spatial per image
#define CODE_CHUNK 32
#define FIX_TAU 1e-3f     // top-2 gap threshold for fp64 fixup

// packed f32x2 helpers (ptxas only emits FFMA2 from explicit PTX)
#define FFMA2(d, a, b, c) \
    asm("fma.rn.f32x2 %0, %1, %2, %3;" : "=l"(d) : "l"(a), "l"(b), "l"(c))
#define ADD2(d, a, b) \
    asm("add.rn.f32x2 %0, %1, %2;" : "=l"(d) : "l"(a), "l"(b))
#define PACK2(d, lo, hi) \
    asm("mov.b64 %0, {%1, %2};" : "=l"(d) : "r"(__float_as_uint(lo)), "r"(__float_as_uint(hi)))
#define UNPACK2(lo, hi, s) do { unsigned _ulo, _uhi; \
    asm("mov.b64 {%0, %1}, %2;" : "=r"(_ulo), "=r"(_uhi) : "l"(s)); \
    lo = __uint_as_float(_ulo); hi = __uint_as_float(_uhi); } while (0)

// ---------------- output layout (flattened tuple, float32) ----------------
static constexpr size_t OFF_LOSS    = 0;
static constexpr size_t OFF_OUT     = 1;                       // 8388608 elems
static constexpr size_t OFF_PERP    = 1 + 8388608ull;
static constexpr size_t OFF_ENC     = OFF_PERP + 1;            // 67108864 elems (8-byte aligned only!)
static constexpr size_t OFF_NEWEMB  = OFF_ENC + (size_t)NTOK * NE;
static constexpr size_t OFF_CLUSTER = OFF_NEWEMB + (size_t)NE * ED;
static constexpr size_t OFF_NEWEMAW = OFF_CLUSTER + NE;

// ---------------- device scratch ----------------
__device__ float g_counts[NE];
__device__ float g_dw[NE * ED];
__device__ float g_loss;
__device__ float g_ne[NE];
__device__ float g_cluster[NE];
__device__ int   g_bid[NTOK];
__device__ int   g_fix_list[NTOK];
__device__ int   g_fix_count;

__device__ __forceinline__ float warpSum(float v) {
    v += __shfl_xor_sync(0xffffffffu, v, 16);
    v += __shfl_xor_sync(0xffffffffu, v, 8);
    v += __shfl_xor_sync(0xffffffffu, v, 4);
    v += __shfl_xor_sync(0xffffffffu, v, 2);
    v += __shfl_xor_sync(0xffffffffu, v, 1);
    return v;
}

// ---------------- init: code norms + zero scratch ----------------
__global__ void vq_init(const float* __restrict__ emb) {
    int e = threadIdx.x;   // 512 threads
    float s = 0.f;
#pragma unroll
    for (int d = 0; d < ED; d++) {
        float v = emb[e * ED + d];
        s = fmaf(v, v, s);
    }
    g_ne[e] = s;
    g_counts[e] = 0.f;
#pragma unroll
    for (int j = 0; j < ED; j++) g_dw[j * NE + e] = 0.f;
    if (e == 0) { g_loss = 0.f; g_fix_count = 0; }
}

// ---------------- fused: zero enc rows + FFMA2 argmin + all outputs ----------------
__global__ __launch_bounds__(128)
void vq_fused(const float* __restrict__ x, const float* __restrict__ emb,
              float* __restrict__ out) {
    __shared__ __align__(16) float es[CODE_CHUNK * ED];   // 8 KB code chunk [c][d]
    __shared__ float nes[CODE_CHUNK];

    const int t   = threadIdx.x;
    const int blk = blockIdx.x;
    const int b   = blk >> 5;           // image index
    const int s0  = (blk & 31) * 128;   // spatial offset
    const int n0  = blk * 128;          // block token base

    // Zero this block's 128 encodings rows (contiguous 256 KB, coalesced).
    // OFF_ENC is only 8-byte aligned -> float2 stores, NOT float4.
    {
        float2 z = make_float2(0.f, 0.f);
        float2* enc2 = (float2*)(out + OFF_ENC + (size_t)n0 * NE);
#pragma unroll 8
        for (int i = t; i < 128 * NE / 2; i += 128) enc2[i] = z;
    }

    // Coalesced NCHW loads, packed immediately into 32 f32x2 registers
    const float* xb = x + ((size_t)b * ED) * HW + s0;
    unsigned long long f2[ED / 2];
#pragma unroll
    for (int i = 0; i < ED / 2; i++) {
        float u = xb[(size_t)(2 * i)     * HW + t];
        float v = xb[(size_t)(2 * i + 1) * HW + t];
        PACK2(f2[i], u, v);
    }

    float best = 3.4e38f, second = 3.4e38f;
    int   bid  = 0;

    for (int c0 = 0; c0 < NE; c0 += CODE_CHUNK) {
        __syncthreads();
#pragma unroll
        for (int k = 0; k < (CODE_CHUNK * ED / 128); k++)
            es[k * 128 + t] = emb[c0 * ED + k * 128 + t];
        if (t < CODE_CHUNK) nes[t] = g_ne[c0 + t];
        __syncthreads();

        for (int c = 0; c < CODE_CHUNK; c++) {
            const ulonglong2* e2 = (const ulonglong2*)(es + c * ED);  // broadcast LDS.128
            unsigned long long a0 = 0, a1 = 0, a2 = 0, a3 = 0;
#pragma unroll
            for (int j = 0; j < 8; j++) {
                ulonglong2 ev0 = e2[2 * j];       // d = 8j .. 8j+3
                ulonglong2 ev1 = e2[2 * j + 1];   // d = 8j+4 .. 8j+7
                FFMA2(a0, f2[4 * j + 0], ev0.x, a0);
                FFMA2(a1, f2[4 * j + 1], ev0.y, a1);
                FFMA2(a2, f2[4 * j + 2], ev1.x, a2);
                FFMA2(a3, f2[4 * j + 3], ev1.y, a3);
            }
            ADD2(a0, a0, a2);
            ADD2(a1, a1, a3);
            ADD2(a0, a0, a1);
            float lo, hi; UNPACK2(lo, hi, a0);
            float dist = fmaf(-2.f, lo + hi, nes[c]);
            if (dist < best)        { second = best; best = dist; bid = c0 + c; }
            else if (dist < second) { second = dist; }
        }
    }

    const int n = n0 + t;
    g_bid[n] = bid;
    if (second - best < FIX_TAU) {
        int i = atomicAdd(&g_fix_count, 1);
        g_fix_list[i] = n;
    }

    // one-hot (own block's rows, zeroed above; __syncthreads in loop ordered it)
    out[OFF_ENC + (size_t)n * NE + bid] = 1.0f;

    // cluster count + dw scatter
    atomicAdd(&g_counts[bid], 1.0f);
#pragma unroll
    for (int i = 0; i < ED / 2; i++) {
        float u, v; UNPACK2(u, v, f2[i]);
        atomicAdd(&g_dw[bid * ED + 2 * i],     u);
        atomicAdd(&g_dw[bid * ED + 2 * i + 1], v);
    }

    // straight-through output (NCHW) + commitment-loss partial
    float lsum = 0.f;
    const float4* ev4 = (const float4*)(emb + (size_t)bid * ED);
    float* ob = out + OFF_OUT + ((size_t)b * ED) * HW + s0;
#pragma unroll
    for (int j = 0; j < 16; j++) {
        float4 ev = __ldg(ev4 + j);
        float u0, u1, u2, u3;
        UNPACK2(u0, u1, f2[2 * j]);
        UNPACK2(u2, u3, f2[2 * j + 1]);
        float d0 = ev.x - u0;
        float d1 = ev.y - u1;
        float d2 = ev.z - u2;
        float d3 = ev.w - u3;
        lsum += d0 * d0 + d1 * d1 + d2 * d2 + d3 * d3;
        ob[(size_t)(4 * j + 0) * HW + t] = u0 + d0;   // fl(f + fl(q-f))
        ob[(size_t)(4 * j + 1) * HW + t] = u1 + d1;
        ob[(size_t)(4 * j + 2) * HW + t] = u2 + d2;
        ob[(size_t)(4 * j + 3) * HW + t] = u3 + d3;
    }
    lsum = warpSum(lsum);
    if ((t & 31) == 0) atomicAdd(&g_loss, lsum);
}

// ---------------- fixup: fp64 re-argmin of near-ties + delta patching ----------------
__global__ void vq_fixup(const float* __restrict__ x, const float* __restrict__ emb,
                         float* __restrict__ out) {
    const int lane = threadIdx.x & 31;
    const int gw   = (blockIdx.x * blockDim.x + threadIdx.x) >> 5;
    const int nw   = (gridDim.x * blockDim.x) >> 5;
    const int cnt  = g_fix_count;

    for (int i = gw; i < cnt; i += nw) {
        const int n = g_fix_list[i];
        const int b = n >> 12;
        const int s = n & 4095;

        float f[ED];
#pragma unroll
        for (int d = 0; d < ED; d++)
            f[d] = x[((size_t)b * ED + d) * HW + s];

        double sf = 0.0;
#pragma unroll
        for (int d = 0; d < ED; d++) sf = fma((double)f[d], (double)f[d], sf);

        float bestd = 3.4e38f;
        int   bestc = NE;
        for (int j = 0; j < NE / 32; j++) {
            const int c = lane + 32 * j;
            const float* e = emb + (size_t)c * ED;
            double dot = 0.0, se = 0.0;
#pragma unroll
            for (int d = 0; d < ED; d++) {
                double ev = (double)e[d];
                dot = fma((double)f[d], ev, dot);
                se  = fma(ev, ev, se);
            }
            float t1  = (float)(sf + se);
            float t2  = (float)(2.0 * dot);
            float d32 = t1 - t2;                    // fp32 rounding like reference
            if (d32 < bestd || (d32 == bestd && c < bestc)) { bestd = d32; bestc = c; }
        }
#pragma unroll
        for (int off = 16; off >= 1; off >>= 1) {
            float od = __shfl_xor_sync(0xffffffffu, bestd, off);
            int   oc = __shfl_xor_sync(0xffffffffu, bestc, off);
            if (od < bestd || (od == bestd && oc < bestc)) { bestd = od; bestc = oc; }
        }
        bestc = __shfl_sync(0xffffffffu, bestc, 0);

        const int oldb = g_bid[n];
        if (bestc != oldb) {
            if (lane == 0) {
                g_bid[n] = bestc;
                out[OFF_ENC + (size_t)n * NE + oldb]  = 0.0f;
                out[OFF_ENC + (size_t)n * NE + bestc] = 1.0f;
                atomicAdd(&g_counts[oldb], -1.0f);
                atomicAdd(&g_counts[bestc], 1.0f);
            }
            float delta = 0.f;
            for (int d = lane; d < ED; d += 32) {
                float eo = emb[(size_t)oldb  * ED + d];
                float en = emb[(size_t)bestc * ED + d];
                atomicAdd(&g_dw[oldb  * ED + d], -f[d]);
                atomicAdd(&g_dw[bestc * ED + d],  f[d]);
                float dn = en - f[d];
                float dold = eo - f[d];
                delta += dn * dn - dold * dold;
                out[OFF_OUT + ((size_t)b * ED + d) * HW + s] = f[d] + dn;
            }
            delta = warpSum(delta);
            if (lane == 0) atomicAdd(&g_loss, delta);
        }
    }
}

// ---------------- finalize A: scalars + cluster (single block) ----------------
__global__ void vq_final_a(const float* __restrict__ ecs, float* __restrict__ out) {
    __shared__ float red[16];
    __shared__ float kkb;

    const int e = threadIdx.x;     // 512 threads
    const int lane = e & 31, w = e >> 5;

    float cnt = g_counts[e];
    float c   = ecs[e] * 0.99f + 0.01f * cnt;

    float s = warpSum(c);
    if (lane == 0) red[w] = s;
    __syncthreads();
    if (w == 0) {
        float v = (lane < 16) ? red[lane] : 0.f;
        v = warpSum(v);
        if (lane == 0) kkb = v;
    }
    __syncthreads();
    const float k = kkb;

    float cs = (c + 1e-5f) / (k + 512.f * 1e-5f) * k;   // Laplace smoothing
    g_cluster[e] = cs;
    out[OFF_CLUSTER + e] = cs;

    float p = cnt * (1.f / 131072.f);
    float term = p * logf(p + 1e-10f);
    float s2 = warpSum(term);
    __syncthreads();
    if (lane == 0) red[w] = s2;
    __syncthreads();
    if (e == 0) {
        float v = 0.f;
        for (int i = 0; i < 16; i++) v += red[i];
        out[OFF_PERP] = expf(-v);
        out[OFF_LOSS] = 0.25f * g_loss * (1.f / 8388608.f);
    }
}

// ---------------- finalize B: new_ema_w / new_embedding (parallel) ----------------
__global__ void vq_final_b(const float* __restrict__ ema_w, float* __restrict__ out) {
    const int m = blockIdx.x * 512 + threadIdx.x;   // 64 blocks x 512 = 32768
    float wv = ema_w[m] * 0.99f + 0.01f * g_dw[m];
    out[OFF_NEWEMAW + m] = wv;
    out[OFF_NEWEMB  + m] = wv / g_cluster[m >> 6];
}

// ---------------- launch ----------------
extern "C" void kernel_launch(void* const* d_in, const int* in_sizes, int n_in,
                              void* d_out, int out_size) {
    const float* x     = (const float*)d_in[0];
    const float* emb   = (const float*)d_in[1];
    const float* ema_w = (const float*)d_in[2];
    const float* ecs   = (const float*)d_in[3];
    float* out = (float*)d_out;

    vq_init<<<1, NE>>>(emb);
    vq_fused<<<NTOK / 128, 128>>>(x, emb, out);
    vq_fixup<<<148, 128>>>(x, emb, out);
    vq_final_a<<<1, NE>>>(ecs, out);
    vq_final_b<<<64, 512>>>(ema_w, out);
}